// round 7
// baseline (speedup 1.0000x reference)
#include <cuda_runtime.h>
#include <cuda_fp16.h>
#include <cstdint>

// ---------------- problem constants ----------------
#define NSAMP   131072
#define INF     8
#define NPCE    495
#define KPAD    512
#define NOUT    256
#define MTILE   128          // CTA rows
#define NTILE   256          // CTA cols (full output width)
#define KC      32           // K per chunk
#define NCHUNK  (KPAD / KC)  // 16
#define NTHREADS 256         // 8 warps: 2(m) x 4(n), each 64m x 64n

// A staged k-major: 32 k-rows x 128 m halves, row stride 272B (17 x 16B)
#define AROWB   272
#define ABUF_BYTES (KC * AROWB)          // 8704
// B staged n-major: 256 n-rows x 32 k halves, row stride 80B
#define BROWB   80
#define BBUF_BYTES (NOUT * BROWB)        // 20480

// smem byte layout (dynamic)
#define OFF_MI  0                        // 512*4 = 2048
#define OFF_H   2048                     // 40 x 128 floats = 20480 -> 22528
#define OFF_A   22528                    // 2 * 8704  -> 39936
#define OFF_B   39936                    // 2 * 20480 -> 80896
#define SMEM_BYTES 80896

// fp16 weights, zero-padded K, plain [NOUT][KPAD] (validated R3/R4 path)
__device__ __half w16g[NOUT * KPAD];

__global__ void convert_w_kernel(const float* __restrict__ wgt) {
    int idx = blockIdx.x * blockDim.x + threadIdx.x;   // 131072 total
    int n = idx >> 9, k = idx & (KPAD - 1);
    w16g[idx] = __float2half(k < NPCE ? wgt[n * NPCE + k] : 0.0f);
}

static __device__ __forceinline__ uint32_t smem_u32(const void* p) {
    uint32_t a;
    asm("{ .reg .u64 t; cvta.to.shared.u64 t, %1; cvt.u32.u64 %0, t; }" : "=r"(a) : "l"(p));
    return a;
}

static __device__ __forceinline__ void cp_async16(uint32_t dst, const void* src) {
    asm volatile("cp.async.ca.shared.global [%0], [%1], 16;" :: "r"(dst), "l"(src));
}

#define CP_COMMIT() asm volatile("cp.async.commit_group;" ::: "memory")
#define CP_WAIT0()  asm volatile("cp.async.wait_group 0;" ::: "memory")

static __device__ __forceinline__ void ldm_x4(uint32_t& r0, uint32_t& r1,
                                              uint32_t& r2, uint32_t& r3, uint32_t addr) {
    asm volatile("ldmatrix.sync.aligned.m8n8.x4.shared.b16 {%0,%1,%2,%3}, [%4];"
                 : "=r"(r0), "=r"(r1), "=r"(r2), "=r"(r3) : "r"(addr));
}

static __device__ __forceinline__ void ldm_x4_trans(uint32_t& r0, uint32_t& r1,
                                                    uint32_t& r2, uint32_t& r3, uint32_t addr) {
    asm volatile("ldmatrix.sync.aligned.m8n8.x4.trans.shared.b16 {%0,%1,%2,%3}, [%4];"
                 : "=r"(r0), "=r"(r1), "=r"(r2), "=r"(r3) : "r"(addr));
}

static __device__ __forceinline__ void mma16816(float& c0, float& c1, float& c2, float& c3,
                                                uint32_t a0, uint32_t a1, uint32_t a2, uint32_t a3,
                                                uint32_t b0, uint32_t b1) {
    asm volatile(
        "mma.sync.aligned.m16n8k16.row.col.f32.f16.f16.f32 "
        "{%0,%1,%2,%3}, {%4,%5,%6,%7}, {%8,%9}, {%0,%1,%2,%3};"
        : "+f"(c0), "+f"(c1), "+f"(c2), "+f"(c3)
        : "r"(a0), "r"(a1), "r"(a2), "r"(a3), "r"(b0), "r"(b1));
}

extern __shared__ char smem[];

__global__ void __launch_bounds__(NTHREADS, 1)
pce_mma_kernel(const float* __restrict__ x, const int* __restrict__ mi,
               float* __restrict__ out)
{
    const int tid  = threadIdx.x;
    const int wid  = tid >> 5;
    const int lane = tid & 31;
    const int m0   = blockIdx.x * MTILE;

    const uint32_t sbase = smem_u32(smem);
    unsigned* mi_s = (unsigned*)(smem + OFF_MI);
    float*    ht   = (float*)(smem + OFF_H);     // HT[off][m], stride 128 floats

    // ---- pack multi-indices: <= 4 nonzero (dim, order) entries, 8-bit slots ----
    for (int t = tid; t < KPAD; t += NTHREADS) {
        unsigned packed = 0;
        if (t < NPCE) {
            int slot = 0;
            #pragma unroll
            for (int j = 0; j < INF; j++) {
                int o = mi[t * INF + j];
                if (o > 0) { packed |= (unsigned)(j * 5 + o) << (8 * slot); slot++; }
            }
        }
        mi_s[t] = packed;
    }

    // ---- normalized Hermite table, transposed HT[j][m] ----
    if (tid < MTILE) {
        const float4* xr = (const float4*)(x + (size_t)(m0 + tid) * INF);
        float4 xa = xr[0], xb = xr[1];
        float vx[8] = {xa.x, xa.y, xa.z, xa.w, xb.x, xb.y, xb.z, xb.w};
        #pragma unroll
        for (int j = 0; j < INF; j++) {
            float v  = vx[j];
            float h2 = v * v - 1.f;
            float h3 = v * h2 - 2.f * v;
            float h4 = v * h3 - 3.f * h2;
            ht[(j * 5 + 0) * MTILE + tid] = 1.f;
            ht[(j * 5 + 1) * MTILE + tid] = v;
            ht[(j * 5 + 2) * MTILE + tid] = h2 * 0.70710678118654752f;
            ht[(j * 5 + 3) * MTILE + tid] = h3 * 0.40824829046386302f;
            ht[(j * 5 + 4) * MTILE + tid] = h4 * 0.20412414523193151f;
        }
    }

    // ---- pipeline helpers (validated R3/R4 structures) ----
    auto load_B = [&](int c, int buf) {
        // 256 n-rows x 64B = 1024 x 16B chunks, 4 per thread
        const uint32_t bdst = sbase + OFF_B + buf * BBUF_BYTES;
        #pragma unroll
        for (int j = 0; j < 4; j++) {
            int idx = tid + j * NTHREADS;        // 0..1023
            int n = idx >> 2, g = idx & 3;
            cp_async16(bdst + n * BROWB + g * 16,
                       w16g + (size_t)n * KPAD + c * KC + g * 8);
        }
    };

    auto gen_psi = [&](int c, int buf) {
        // A tile k-major [32 k][128 m]; k warp-uniform, m per lane
        const int k0 = c * KC;
        #pragma unroll
        for (int i = 0; i < 16; i++) {
            int idx = tid + i * NTHREADS;        // 0..4095
            int k = idx >> 7, m = idx & 127;
            unsigned p = mi_s[k0 + k];
            float v = ht[(p & 255) * MTILE + m] * ht[((p >> 8) & 255) * MTILE + m]
                    * ht[((p >> 16) & 255) * MTILE + m] * ht[(p >> 24) * MTILE + m];
            *(__half*)(smem + OFF_A + buf * ABUF_BYTES + k * AROWB + m * 2)
                = __float2half(v);
        }
    };

    // ---- warp tiling: 2(m) x 4(n), each 64m x 64n ----
    const int warp_m = wid >> 2;   // 0..1
    const int warp_n = wid & 3;    // 0..3

    float acc[4][8][4];
    #pragma unroll
    for (int a = 0; a < 4; a++)
        #pragma unroll
        for (int b = 0; b < 8; b++)
            #pragma unroll
            for (int r = 0; r < 4; r++) acc[a][b][r] = 0.f;

    __syncthreads();           // HT + mi_s ready
    load_B(0, 0);
    CP_COMMIT();
    gen_psi(0, 0);
    CP_WAIT0();
    __syncthreads();           // stage 0 ready

    const int a_row_off = (lane & 7) + ((lane >> 4) & 1) * 8;
    const int a_m_off   = ((lane >> 3) & 1) * 8;

    for (int c = 0; c < NCHUNK; c++) {
        const int cb = c & 1;
        const uint32_t abase = sbase + OFF_A + cb * ABUF_BYTES;
        const uint32_t b_base = sbase + OFF_B + cb * BBUF_BYTES
                              + (warp_n * 64 + ((lane >> 4) * 8) + (lane & 7)) * BROWB
                              + ((lane >> 3) & 1) * 16;

        if (c + 1 < NCHUNK) {
            load_B(c + 1, cb ^ 1);
            CP_COMMIT();
        }

        // ---- kb = 0 ----
        {
            uint32_t af[4][4], bf[4][4];
            #pragma unroll
            for (int mb = 0; mb < 4; mb++)
                ldm_x4_trans(af[mb][0], af[mb][1], af[mb][2], af[mb][3],
                             abase + a_row_off * AROWB
                                   + (warp_m * 64 + mb * 16 + a_m_off) * 2);
            #pragma unroll
            for (int np = 0; np < 4; np++)
                ldm_x4(bf[np][0], bf[np][1], bf[np][2], bf[np][3],
                       b_base + np * 16 * BROWB);
            #pragma unroll
            for (int mb = 0; mb < 4; mb++)
                #pragma unroll
                for (int nb = 0; nb < 8; nb++)
                    mma16816(acc[mb][nb][0], acc[mb][nb][1], acc[mb][nb][2], acc[mb][nb][3],
                             af[mb][0], af[mb][1], af[mb][2], af[mb][3],
                             bf[nb >> 1][(nb & 1) * 2], bf[nb >> 1][(nb & 1) * 2 + 1]);
        }

        // overlap: next chunk's psi while kb0 MMAs drain
        if (c + 1 < NCHUNK) gen_psi(c + 1, cb ^ 1);

        // ---- kb = 1 ----
        {
            uint32_t af[4][4], bf[4][4];
            #pragma unroll
            for (int mb = 0; mb < 4; mb++)
                ldm_x4_trans(af[mb][0], af[mb][1], af[mb][2], af[mb][3],
                             abase + (16 + a_row_off) * AROWB
                                   + (warp_m * 64 + mb * 16 + a_m_off) * 2);
            #pragma unroll
            for (int np = 0; np < 4; np++)
                ldm_x4(bf[np][0], bf[np][1], bf[np][2], bf[np][3],
                       b_base + np * 16 * BROWB + 32);
            #pragma unroll
            for (int mb = 0; mb < 4; mb++)
                #pragma unroll
                for (int nb = 0; nb < 8; nb++)
                    mma16816(acc[mb][nb][0], acc[mb][nb][1], acc[mb][nb][2], acc[mb][nb][3],
                             af[mb][0], af[mb][1], af[mb][2], af[mb][3],
                             bf[nb >> 1][(nb & 1) * 2], bf[nb >> 1][(nb & 1) * 2 + 1]);
        }

        if (c + 1 < NCHUNK) CP_WAIT0();
        __syncthreads();   // stage c+1 fully staged before its reads; WAR safe
    }

    // ---- epilogue: direct fp32 stores ----
    {
        const int mw = m0 + warp_m * 64;
        const int nw = warp_n * 64;
        const int rq = lane >> 2;
        const int cq = 2 * (lane & 3);
        #pragma unroll
        for (int mb = 0; mb < 4; mb++) {
            #pragma unroll
            for (int nb = 0; nb < 8; nb++) {
                const int row = mw + mb * 16 + rq;
                const int col = nw + nb * 8 + cq;
                *(float2*)(out + (size_t)row * NOUT + col)
                    = make_float2(acc[mb][nb][0], acc[mb][nb][1]);
                *(float2*)(out + (size_t)(row + 8) * NOUT + col)
                    = make_float2(acc[mb][nb][2], acc[mb][nb][3]);
            }
        }
    }
}

extern "C" void kernel_launch(void* const* d_in, const int* in_sizes, int n_in,
                              void* d_out, int out_size) {
    const float* x   = (const float*)d_in[0];
    const float* wgt = (const float*)d_in[1];
    const int*   mi  = (const int*)d_in[2];
    float* out = (float*)d_out;

    convert_w_kernel<<<(NOUT * KPAD) / 256, 256>>>(wgt);

    cudaFuncSetAttribute(pce_mma_kernel,
                         cudaFuncAttributeMaxDynamicSharedMemorySize, SMEM_BYTES);
    pce_mma_kernel<<<NSAMP / MTILE, NTHREADS, SMEM_BYTES>>>(x, mi, out);
}

// round 8
// speedup vs baseline: 1.3645x; 1.3645x over previous
#include <cuda_runtime.h>
#include <cuda_fp16.h>
#include <cstdint>

// ---------------- problem constants ----------------
#define NSAMP   131072
#define INF     8
#define NPCE    495
#define KPAD    512
#define NOUT    256
#define MTILE   128          // GEMM CTA rows
#define KC      64           // K per chunk
#define NCHUNK  (KPAD / KC)  // 8

// GEMM smem: A k-major [64 k][128 m] halves, row stride 272B (17x16B granules)
#define AROWB   272
#define ABUF_BYTES (KC * AROWB)          // 17408
// B n-major [256 n][64 k] halves, row stride 144B (9x16B granules)
#define BROWB   144
#define BBUF_BYTES (NOUT * BROWB)        // 36864
#define OFF_A   0
#define OFF_B   (2 * ABUF_BYTES)         // 34816
#define GEMM_SMEM (OFF_B + 2 * BBUF_BYTES)   // 108544

// psi_gen smem
#define PG_OFF_MI 0                      // 512*4
#define PG_OFF_H  2048                   // 40 x 128 floats
#define PG_SMEM   22528

// fp16 weights, zero-padded K, [NOUT][KPAD]
__device__ __half w16g[NOUT * KPAD];
// psi staged fp16, [k][m] layout (k-major rows of 131072 halves)
__device__ __align__(16) __half psi16[(size_t)KPAD * NSAMP];

__global__ void convert_w_kernel(const float* __restrict__ wgt) {
    int idx = blockIdx.x * blockDim.x + threadIdx.x;   // 131072 total
    int n = idx >> 9, k = idx & (KPAD - 1);
    w16g[idx] = __float2half(k < NPCE ? wgt[n * NPCE + k] : 0.0f);
}

static __device__ __forceinline__ uint32_t smem_u32(const void* p) {
    uint32_t a;
    asm("{ .reg .u64 t; cvta.to.shared.u64 t, %1; cvt.u32.u64 %0, t; }" : "=r"(a) : "l"(p));
    return a;
}

// ================= psi generation: one block per 128-sample tile =============
__global__ void __launch_bounds__(256)
psi_gen_kernel(const float* __restrict__ x, const int* __restrict__ mi)
{
    __shared__ unsigned mi_s[KPAD];
    __shared__ float    ht[40 * MTILE];     // HT[off][m]
    const int tid = threadIdx.x;
    const int m0  = blockIdx.x * MTILE;

    // pack multi-indices: <= 4 nonzero (dim, order) entries, 8-bit slots
    for (int t = tid; t < KPAD; t += 256) {
        unsigned packed = 0;
        if (t < NPCE) {
            int slot = 0;
            #pragma unroll
            for (int j = 0; j < INF; j++) {
                int o = mi[t * INF + j];
                if (o > 0) { packed |= (unsigned)(j * 5 + o) << (8 * slot); slot++; }
            }
        }
        mi_s[t] = packed;
    }

    // normalized Hermite table, transposed HT[j][m]
    if (tid < MTILE) {
        const float4* xr = (const float4*)(x + (size_t)(m0 + tid) * INF);
        float4 xa = xr[0], xb = xr[1];
        float vx[8] = {xa.x, xa.y, xa.z, xa.w, xb.x, xb.y, xb.z, xb.w};
        #pragma unroll
        for (int j = 0; j < INF; j++) {
            float v  = vx[j];
            float h2 = v * v - 1.f;
            float h3 = v * h2 - 2.f * v;
            float h4 = v * h3 - 3.f * h2;
            ht[(j * 5 + 0) * MTILE + tid] = 1.f;
            ht[(j * 5 + 1) * MTILE + tid] = v;
            ht[(j * 5 + 2) * MTILE + tid] = h2 * 0.70710678118654752f;
            ht[(j * 5 + 3) * MTILE + tid] = h3 * 0.40824829046386302f;
            ht[(j * 5 + 4) * MTILE + tid] = h4 * 0.20412414523193151f;
        }
    }
    __syncthreads();

    // 512 k-rows x 64 m-pairs; warp-uniform k, coalesced half2 stores
    const float2* ht2 = (const float2*)ht;    // [off][mp], 64 float2 per row
    #pragma unroll 4
    for (int it = 0; it < 128; it++) {
        int idx = it * 256 + tid;             // 0..32767
        int k = idx >> 6, mp = idx & 63;
        unsigned p = mi_s[k];
        float2 a = ht2[(p & 255) * 64 + mp];  // p==0 -> HT row 0 = (1,1)
        p >>= 8;
        while (p) {                           // warp-uniform slot-count skip
            float2 b = ht2[(p & 255) * 64 + mp];
            a.x *= b.x; a.y *= b.y;
            p >>= 8;
        }
        *(__half2*)(psi16 + (size_t)k * NSAMP + m0 + 2 * mp)
            = __floats2half2_rn(a.x, a.y);
    }
}

// ================= GEMM: psi16[k][m] (x) w16g[n][k] -> out[m][n] =============
static __device__ __forceinline__ void cp_async16(uint32_t dst, const void* src) {
    asm volatile("cp.async.ca.shared.global [%0], [%1], 16;" :: "r"(dst), "l"(src));
}
#define CP_COMMIT() asm volatile("cp.async.commit_group;" ::: "memory")
#define CP_WAIT0()  asm volatile("cp.async.wait_group 0;" ::: "memory")

static __device__ __forceinline__ void ldm_x4(uint32_t& r0, uint32_t& r1,
                                              uint32_t& r2, uint32_t& r3, uint32_t addr) {
    asm volatile("ldmatrix.sync.aligned.m8n8.x4.shared.b16 {%0,%1,%2,%3}, [%4];"
                 : "=r"(r0), "=r"(r1), "=r"(r2), "=r"(r3) : "r"(addr));
}
static __device__ __forceinline__ void ldm_x4_trans(uint32_t& r0, uint32_t& r1,
                                                    uint32_t& r2, uint32_t& r3, uint32_t addr) {
    asm volatile("ldmatrix.sync.aligned.m8n8.x4.trans.shared.b16 {%0,%1,%2,%3}, [%4];"
                 : "=r"(r0), "=r"(r1), "=r"(r2), "=r"(r3) : "r"(addr));
}
static __device__ __forceinline__ void mma16816(float& c0, float& c1, float& c2, float& c3,
                                                uint32_t a0, uint32_t a1, uint32_t a2, uint32_t a3,
                                                uint32_t b0, uint32_t b1) {
    asm volatile(
        "mma.sync.aligned.m16n8k16.row.col.f32.f16.f16.f32 "
        "{%0,%1,%2,%3}, {%4,%5,%6,%7}, {%8,%9}, {%0,%1,%2,%3};"
        : "+f"(c0), "+f"(c1), "+f"(c2), "+f"(c3)
        : "r"(a0), "r"(a1), "r"(a2), "r"(a3), "r"(b0), "r"(b1));
}

extern __shared__ char smem[];

__global__ void __launch_bounds__(512, 1)
pce_gemm_kernel(float* __restrict__ out)
{
    const int tid  = threadIdx.x;
    const int wid  = tid >> 5;
    const int lane = tid & 31;
    const int m0   = blockIdx.x * MTILE;

    const uint32_t sbase = smem_u32(smem);

    auto load_A = [&](int c, int buf) {
        // 64 k-rows x 256B from psi16[k][m0..m0+128); 1024 granules / 512 thr
        const uint32_t adst = sbase + OFF_A + buf * ABUF_BYTES;
        #pragma unroll
        for (int j = 0; j < 2; j++) {
            int idx = tid + j * 512;             // 0..1023
            int row = idx >> 4, g = idx & 15;
            cp_async16(adst + row * AROWB + g * 16,
                       psi16 + (size_t)(c * KC + row) * NSAMP + m0 + g * 8);
        }
    };
    auto load_B = [&](int c, int buf) {
        // 256 n-rows x 128B from w16g; 2048 granules / 512 thr
        const uint32_t bdst = sbase + OFF_B + buf * BBUF_BYTES;
        #pragma unroll
        for (int j = 0; j < 4; j++) {
            int idx = tid + j * 512;             // 0..2047
            int n = idx >> 3, g = idx & 7;
            cp_async16(bdst + n * BROWB + g * 16,
                       w16g + (size_t)n * KPAD + c * KC + g * 8);
        }
    };

    // warp tiling: 4(m) x 4(n), each 32m x 64n  (R4-validated)
    const int warp_m = wid >> 2;   // 0..3
    const int warp_n = wid & 3;    // 0..3

    float acc[2][8][4];
    #pragma unroll
    for (int a = 0; a < 2; a++)
        #pragma unroll
        for (int b = 0; b < 8; b++)
            #pragma unroll
            for (int r = 0; r < 4; r++) acc[a][b][r] = 0.f;

    load_A(0, 0);
    load_B(0, 0);
    CP_COMMIT();
    CP_WAIT0();
    __syncthreads();

    const int a_row_off = (lane & 7) + ((lane >> 4) & 1) * 8;
    const int a_m_off   = ((lane >> 3) & 1) * 8;

    for (int c = 0; c < NCHUNK; c++) {
        const int cb = c & 1;
        const uint32_t abase = sbase + OFF_A + cb * ABUF_BYTES;
        const uint32_t b_base = sbase + OFF_B + cb * BBUF_BYTES
                              + (warp_n * 64 + ((lane >> 4) * 8) + (lane & 7)) * BROWB
                              + ((lane >> 3) & 1) * 16;

        if (c + 1 < NCHUNK) {
            load_A(c + 1, cb ^ 1);
            load_B(c + 1, cb ^ 1);
            CP_COMMIT();
        }

        #pragma unroll
        for (int kb = 0; kb < 4; kb++) {     // four k16 blocks per chunk
            uint32_t af[2][4], bf[4][4];
            #pragma unroll
            for (int mb = 0; mb < 2; mb++)
                ldm_x4_trans(af[mb][0], af[mb][1], af[mb][2], af[mb][3],
                             abase + (kb * 16 + a_row_off) * AROWB
                                   + (warp_m * 32 + mb * 16 + a_m_off) * 2);
            #pragma unroll
            for (int np = 0; np < 4; np++)
                ldm_x4(bf[np][0], bf[np][1], bf[np][2], bf[np][3],
                       b_base + np * 16 * BROWB + kb * 32);
            #pragma unroll
            for (int mb = 0; mb < 2; mb++)
                #pragma unroll
                for (int nb = 0; nb < 8; nb++)
                    mma16816(acc[mb][nb][0], acc[mb][nb][1], acc[mb][nb][2], acc[mb][nb][3],
                             af[mb][0], af[mb][1], af[mb][2], af[mb][3],
                             bf[nb >> 1][(nb & 1) * 2], bf[nb >> 1][(nb & 1) * 2 + 1]);
        }

        if (c + 1 < NCHUNK) CP_WAIT0();
        __syncthreads();
    }

    // epilogue: direct fp32 stores (R4-validated)
    {
        const int mw = m0 + warp_m * 32;
        const int nw = warp_n * 64;
        const int rq = lane >> 2;
        const int cq = 2 * (lane & 3);
        #pragma unroll
        for (int mb = 0; mb < 2; mb++) {
            #pragma unroll
            for (int nb = 0; nb < 8; nb++) {
                const int row = mw + mb * 16 + rq;
                const int col = nw + nb * 8 + cq;
                *(float2*)(out + (size_t)row * NOUT + col)
                    = make_float2(acc[mb][nb][0], acc[mb][nb][1]);
                *(float2*)(out + (size_t)(row + 8) * NOUT + col)
                    = make_float2(acc[mb][nb][2], acc[mb][nb][3]);
            }
        }
    }
}

extern "C" void kernel_launch(void* const* d_in, const int* in_sizes, int n_in,
                              void* d_out, int out_size) {
    const float* x   = (const float*)d_in[0];
    const float* wgt = (const float*)d_in[1];
    const int*   mi  = (const int*)d_in[2];
    float* out = (float*)d_out;

    convert_w_kernel<<<(NOUT * KPAD) / 256, 256>>>(wgt);
    psi_gen_kernel<<<NSAMP / MTILE, 256>>>(x, mi);

    cudaFuncSetAttribute(pce_gemm_kernel,
                         cudaFuncAttributeMaxDynamicSharedMemorySize, GEMM_SMEM);
    pce_gemm_kernel<<<NSAMP / MTILE, 512, GEMM_SMEM>>>(out);
}